// round 5
// baseline (speedup 1.0000x reference)
#include <cuda_runtime.h>
#include <math.h>
#include <float.h>

#define Nn 100000
#define Ff 256
#define Hh 64
#define Ee 800000
#define Rr 7
#define TILE 64
#define BS 68
#define TR 128
#define BS2 132

typedef unsigned long long ull;

__device__ float d_h[Nn * Hh];
__device__ float d_A[Nn * Hh];
__device__ float d_B[Nn * Hh];
__device__ float d_S[Nn * Hh];
__device__ float d_cnt[Nn];
__device__ float d_C[Rr * Hh];
__device__ float d_colsum[Hh];
__device__ int   d_colmax[Hh];

__device__ __forceinline__ ull pk2(float a, float b) {
    ull r; asm("mov.b64 %0, {%1,%2};" : "=l"(r) : "f"(a), "f"(b)); return r;
}
__device__ __forceinline__ float2 upk2(ull v) {
    float2 f; asm("mov.b64 {%0,%1}, %2;" : "=f"(f.x), "=f"(f.y) : "l"(v)); return f;
}
__device__ __forceinline__ void fma2(ull &d, ull a, ull b) {
    asm("fma.rn.f32x2 %0, %1, %2, %0;" : "+l"(d) : "l"(a), "l"(b));
}
__device__ __forceinline__ void atomicMaxFloat(int* addr, float v) {
    if (v >= 0.f) atomicMax(addr, __float_as_int(v));
    else          atomicMin((unsigned int*)addr, __float_as_uint(v));
}

// colsum/colmax init folded in here (k_init removed)
__global__ void k_relC(const float* __restrict__ rel_emb, const float* __restrict__ Wm1) {
    int t = threadIdx.x;
    if (t < Hh) { d_colsum[t] = 0.f; d_colmax[t] = __float_as_int(-FLT_MAX); }
    if (t >= Rr * Hh) return;
    int r = t / Hh, j = t % Hh;
    float s = 0.f;
    for (int k = 0; k < Hh; k++) s += rel_emb[r * Hh + k] * Wm1[(128 + k) * Hh + j];
    d_C[t] = s;
}

// uniform row-pair GEMM core: 16 rows x 2 cols per thread over a 128x64 tile
#define GEMM_CORE(IBUF, ACC)                                                     \
    _Pragma("unroll 2")                                                          \
    for (int k = 0; k < 64; k++) {                                               \
        ulonglong2 xa = *(const ulonglong2*)((IBUF) + k * BS2 + r0);             \
        ulonglong2 xb = *(const ulonglong2*)((IBUF) + k * BS2 + r0 + 4);         \
        ulonglong2 xc = *(const ulonglong2*)((IBUF) + k * BS2 + r0 + 8);         \
        ulonglong2 xd = *(const ulonglong2*)((IBUF) + k * BS2 + r0 + 12);        \
        float2 w = *(const float2*)(sW + k * 64 + c0);                           \
        ull wd0 = pk2(w.x, w.x), wd1 = pk2(w.y, w.y);                            \
        fma2(ACC[0][0], xa.x, wd0); fma2(ACC[0][1], xa.x, wd1);                  \
        fma2(ACC[1][0], xa.y, wd0); fma2(ACC[1][1], xa.y, wd1);                  \
        fma2(ACC[2][0], xb.x, wd0); fma2(ACC[2][1], xb.x, wd1);                  \
        fma2(ACC[3][0], xb.y, wd0); fma2(ACC[3][1], xb.y, wd1);                  \
        fma2(ACC[4][0], xc.x, wd0); fma2(ACC[4][1], xc.x, wd1);                  \
        fma2(ACC[5][0], xc.y, wd0); fma2(ACC[5][1], xc.y, wd1);                  \
        fma2(ACC[6][0], xd.x, wd0); fma2(ACC[6][1], xd.x, wd1);                  \
        fma2(ACC[7][0], xd.y, wd0); fma2(ACC[7][1], xd.y, wd1);                  \
    }

__global__ __launch_bounds__(256) void k_node(
    const float* __restrict__ X,
    const float* __restrict__ W1, const float* __restrict__ b1,
    const float* __restrict__ g1, const float* __restrict__ be1,
    const float* __restrict__ W2, const float* __restrict__ b2,
    const float* __restrict__ Wm1)
{
    extern __shared__ __align__(16) float sm[];
    float* buf  = sm;                    // 64*BS2
    float* obuf = sm + 64 * BS2;         // 64*BS2
    float* sW   = sm + 128 * BS2;        // 64*64
    __shared__ float sb1[64], sg1[64], sbe1[64], sb2[64];

    int tid = threadIdx.x;
    int n0 = blockIdx.x * TR;
    int nvalid = min(TR, Nn - n0);
    if (tid < 64) { sb1[tid] = b1[tid]; sg1[tid] = g1[tid]; sbe1[tid] = be1[tid]; sb2[tid] = b2[tid]; }

    int tx = tid & 31, ty = tid >> 5;
    int c0 = 2 * tx, r0 = 16 * ty;

    ull acc[8][2];
#pragma unroll
    for (int p = 0; p < 8; p++) { acc[p][0] = 0ull; acc[p][1] = 0ull; }

    // ---- GEMM1: Y = X @ W1, K=256 in 4 chunks ----
    for (int kc = 0; kc < 4; kc++) {
#pragma unroll
        for (int i = 0; i < 8; i++) {
            int f = tid + i * 256;
            int r = f & 127;
            int k4 = (f >> 7) * 4;
            float4 v = make_float4(0.f, 0.f, 0.f, 0.f);
            if (r < nvalid) v = *(const float4*)(X + (size_t)(n0 + r) * Ff + kc * 64 + k4);
            buf[(k4 + 0) * BS2 + r] = v.x;
            buf[(k4 + 1) * BS2 + r] = v.y;
            buf[(k4 + 2) * BS2 + r] = v.z;
            buf[(k4 + 3) * BS2 + r] = v.w;
        }
#pragma unroll
        for (int i = 0; i < 4; i++) {
            int f = tid + i * 256;
            *(float4*)(sW + f * 4) = *(const float4*)(W1 + kc * 64 * 64 + f * 4);
        }
        __syncthreads();
        GEMM_CORE(buf, acc)
        __syncthreads();
    }

    // epilogue 1: y = acc + b1 -> obuf
#pragma unroll
    for (int p = 0; p < 8; p++)
#pragma unroll
        for (int c = 0; c < 2; c++) {
            float2 v = upk2(acc[p][c]);
            float bb = sb1[c0 + c];
            *(float2*)(obuf + (c0 + c) * BS2 + r0 + 2 * p) = make_float2(v.x + bb, v.y + bb);
        }
#pragma unroll
    for (int i = 0; i < 4; i++) {
        int f = tid + i * 256;
        *(float4*)(sW + f * 4) = *(const float4*)(W2 + f * 4);
    }
    __syncthreads();

    // LN + relu: obuf -> buf (128 threads, one row each)
    if (tid < TR) {
        int r = tid;
        float s = 0.f, s2 = 0.f;
        for (int c = 0; c < 64; c++) { float x = obuf[c * BS2 + r]; s += x; s2 += x * x; }
        float mu = s * (1.f / 64.f);
        float var = s2 * (1.f / 64.f) - mu * mu;
        float rs = rsqrtf(var + 1e-5f);
        for (int c = 0; c < 64; c++) {
            float x = obuf[c * BS2 + r];
            buf[c * BS2 + r] = fmaxf((x - mu) * rs * sg1[c] + sbe1[c], 0.f);
        }
    }
    __syncthreads();

    // ---- GEMM2: h = relu(h1n @ W2 + b2) -> obuf ----
    ull a2[8][2];
#pragma unroll
    for (int p = 0; p < 8; p++) { a2[p][0] = 0ull; a2[p][1] = 0ull; }
    GEMM_CORE(buf, a2)
#pragma unroll
    for (int p = 0; p < 8; p++)
#pragma unroll
        for (int c = 0; c < 2; c++) {
            float2 v = upk2(a2[p][c]);
            float bb = sb2[c0 + c];
            *(float2*)(obuf + (c0 + c) * BS2 + r0 + 2 * p) =
                make_float2(fmaxf(v.x + bb, 0.f), fmaxf(v.y + bb, 0.f));
        }
    __syncthreads();

    // store h coalesced; stage Wm1a
#pragma unroll
    for (int i = 0; i < 8; i++) {
        int f = tid + i * 256;
        int r = f >> 4, c4 = (f & 15) * 4;
        if (r < nvalid) {
            float4 v;
            v.x = obuf[(c4 + 0) * BS2 + r]; v.y = obuf[(c4 + 1) * BS2 + r];
            v.z = obuf[(c4 + 2) * BS2 + r]; v.w = obuf[(c4 + 3) * BS2 + r];
            *(float4*)(d_h + (size_t)(n0 + r) * 64 + c4) = v;
        }
    }
#pragma unroll
    for (int i = 0; i < 4; i++) {
        int f = tid + i * 256;
        *(float4*)(sW + f * 4) = *(const float4*)(Wm1 + f * 4);
    }
    __syncthreads();

    // ---- GEMM3: A = h @ Wm1[0:64] -> buf -> d_A ----
    ull a3[8][2];
#pragma unroll
    for (int p = 0; p < 8; p++) { a3[p][0] = 0ull; a3[p][1] = 0ull; }
    GEMM_CORE(obuf, a3)
#pragma unroll
    for (int p = 0; p < 8; p++)
#pragma unroll
        for (int c = 0; c < 2; c++) {
            float2 v = upk2(a3[p][c]);
            *(float2*)(buf + (c0 + c) * BS2 + r0 + 2 * p) = v;
        }
    __syncthreads();
#pragma unroll
    for (int i = 0; i < 8; i++) {
        int f = tid + i * 256;
        int r = f >> 4, c4 = (f & 15) * 4;
        if (r < nvalid) {
            float4 v;
            v.x = buf[(c4 + 0) * BS2 + r]; v.y = buf[(c4 + 1) * BS2 + r];
            v.z = buf[(c4 + 2) * BS2 + r]; v.w = buf[(c4 + 3) * BS2 + r];
            *(float4*)(d_A + (size_t)(n0 + r) * 64 + c4) = v;
        }
    }
#pragma unroll
    for (int i = 0; i < 4; i++) {
        int f = tid + i * 256;
        *(float4*)(sW + f * 4) = *(const float4*)(Wm1 + 64 * 64 + f * 4);
    }
    __syncthreads();

    // ---- GEMM4: B = h @ Wm1[64:128] -> buf -> d_B ----
    ull a4[8][2];
#pragma unroll
    for (int p = 0; p < 8; p++) { a4[p][0] = 0ull; a4[p][1] = 0ull; }
    GEMM_CORE(obuf, a4)
#pragma unroll
    for (int p = 0; p < 8; p++)
#pragma unroll
        for (int c = 0; c < 2; c++) {
            float2 v = upk2(a4[p][c]);
            *(float2*)(buf + (c0 + c) * BS2 + r0 + 2 * p) = v;
        }
    __syncthreads();
#pragma unroll
    for (int i = 0; i < 8; i++) {
        int f = tid + i * 256;
        int r = f >> 4, c4 = (f & 15) * 4;
        if (r < nvalid) {
            float4 v;
            v.x = buf[(c4 + 0) * BS2 + r]; v.y = buf[(c4 + 1) * BS2 + r];
            v.z = buf[(c4 + 2) * BS2 + r]; v.w = buf[(c4 + 3) * BS2 + r];
            *(float4*)(d_B + (size_t)(n0 + r) * 64 + c4) = v;
        }
    }

    // ---- fused init: zero d_S rows and d_cnt for this tile ----
#pragma unroll
    for (int i = 0; i < 8; i++) {
        int f = tid + i * 256;
        int r = f >> 4, c4 = (f & 15) * 4;
        if (r < nvalid)
            *(float4*)(d_S + (size_t)(n0 + r) * 64 + c4) = make_float4(0.f, 0.f, 0.f, 0.f);
    }
    if (tid < TR && tid < nvalid) d_cnt[n0 + tid] = 0.f;
}

__global__ __launch_bounds__(256) void k_edge(
    const float* __restrict__ edges,
    const float* __restrict__ Wm1, const float* __restrict__ bm1)
{
    __shared__ float sC[Rr * 64];
    __shared__ float swl[64], sbm1[64];
    int tid = threadIdx.x;
    for (int i = tid; i < Rr * 64; i += 256) sC[i] = d_C[i];
    if (tid < 64) { swl[tid] = Wm1[192 * 64 + tid]; sbm1[tid] = bm1[tid]; }
    __syncthreads();

    const int half = Ee / 2;
    int g = (blockIdx.x * 256 + tid) >> 4;
    int sub = tid & 15;
    if (g >= half) return;
    int c4 = sub * 4;

    float4 e0 = *(const float4*)(edges + (size_t)g * 4);
    float4 e1 = *(const float4*)(edges + (size_t)(g + half) * 4);
    int s0 = (int)e0.x, d0 = (int)e0.y, r0 = (int)e0.z; float w0 = e0.w;
    int s1 = (int)e1.x, d1 = (int)e1.y, r1 = (int)e1.z; float w1 = e1.w;

    float4 a0 = *(const float4*)(d_A + (size_t)s0 * 64 + c4);
    float4 b0 = *(const float4*)(d_B + (size_t)d0 * 64 + c4);
    float4 a1 = *(const float4*)(d_A + (size_t)s1 * 64 + c4);
    float4 b1 = *(const float4*)(d_B + (size_t)d1 * 64 + c4);

    float4 c0v = *(const float4*)(sC + r0 * 64 + c4);
    float4 c1v = *(const float4*)(sC + r1 * 64 + c4);
    float4 wl = *(const float4*)(swl + c4);
    float4 bm = *(const float4*)(sbm1 + c4);

    float4 v0, v1;
    v0.x = fmaxf(a0.x + b0.x + c0v.x + w0 * wl.x + bm.x, 0.f);
    v0.y = fmaxf(a0.y + b0.y + c0v.y + w0 * wl.y + bm.y, 0.f);
    v0.z = fmaxf(a0.z + b0.z + c0v.z + w0 * wl.z + bm.z, 0.f);
    v0.w = fmaxf(a0.w + b0.w + c0v.w + w0 * wl.w + bm.w, 0.f);
    v1.x = fmaxf(a1.x + b1.x + c1v.x + w1 * wl.x + bm.x, 0.f);
    v1.y = fmaxf(a1.y + b1.y + c1v.y + w1 * wl.y + bm.y, 0.f);
    v1.z = fmaxf(a1.z + b1.z + c1v.z + w1 * wl.z + bm.z, 0.f);
    v1.w = fmaxf(a1.w + b1.w + c1v.w + w1 * wl.w + bm.w, 0.f);

    float* p0 = d_S + (size_t)d0 * 64 + c4;
    float* p1 = d_S + (size_t)d1 * 64 + c4;
    asm volatile("red.global.add.v4.f32 [%0], {%1,%2,%3,%4};"
                 :: "l"(p0), "f"(v0.x), "f"(v0.y), "f"(v0.z), "f"(v0.w) : "memory");
    asm volatile("red.global.add.v4.f32 [%0], {%1,%2,%3,%4};"
                 :: "l"(p1), "f"(v1.x), "f"(v1.y), "f"(v1.z), "f"(v1.w) : "memory");
    if (sub == 0) { atomicAdd(&d_cnt[d0], 1.f); atomicAdd(&d_cnt[d1], 1.f); }
}

__global__ __launch_bounds__(256) void k_agg(
    const float* __restrict__ Wm2, const float* __restrict__ bm2,
    const float* __restrict__ gn,  const float* __restrict__ bn)
{
    __shared__ __align__(16) float buf[64 * BS];
    __shared__ __align__(16) float sW[64 * 64];
    __shared__ float sbm2[64], sgn[64], sbn[64];
    __shared__ float red_s[4 * 64];
    __shared__ float red_m[4 * 64];

    int tid = threadIdx.x;
    int n0 = blockIdx.x * TILE;
    int nvalid = min(TILE, Nn - n0);
    if (tid < 64) { sbm2[tid] = bm2[tid]; sgn[tid] = gn[tid]; sbn[tid] = bn[tid]; }

    for (int i = 0; i < 4; i++) {
        int f = tid + i * 256;
        int r = f & 63;
        int k4 = (f >> 6) * 4;
        float4 v = make_float4(0.f, 0.f, 0.f, 0.f);
        if (r < nvalid) v = *(const float4*)(d_S + (size_t)(n0 + r) * 64 + k4);
        buf[(k4 + 0) * BS + r] = v.x;
        buf[(k4 + 1) * BS + r] = v.y;
        buf[(k4 + 2) * BS + r] = v.z;
        buf[(k4 + 3) * BS + r] = v.w;
    }
    for (int i = 0; i < 4; i++) {
        int f = tid + i * 256;
        *(float4*)(sW + f * 4) = *(const float4*)(Wm2 + f * 4);
    }
    __syncthreads();

    int tx = tid & 31, ty = tid >> 5;
    int c0 = 2 * tx, r0 = 8 * ty;
    ull acc[4][2];
#pragma unroll
    for (int p = 0; p < 4; p++) { acc[p][0] = 0ull; acc[p][1] = 0ull; }
#pragma unroll 4
    for (int k = 0; k < 64; k++) {
        ulonglong2 xa = *(const ulonglong2*)(buf + k * BS + r0);
        ulonglong2 xb = *(const ulonglong2*)(buf + k * BS + r0 + 4);
        float2 w = *(const float2*)(sW + k * 64 + c0);
        ull wd0 = pk2(w.x, w.x), wd1 = pk2(w.y, w.y);
        fma2(acc[0][0], xa.x, wd0); fma2(acc[0][1], xa.x, wd1);
        fma2(acc[1][0], xa.y, wd0); fma2(acc[1][1], xa.y, wd1);
        fma2(acc[2][0], xb.x, wd0); fma2(acc[2][1], xb.x, wd1);
        fma2(acc[3][0], xb.y, wd0); fma2(acc[3][1], xb.y, wd1);
    }
    __syncthreads();

#pragma unroll
    for (int p = 0; p < 4; p++) {
        int rr = r0 + 2 * p;
        float cnt0 = (rr     < nvalid) ? d_cnt[n0 + rr]     : 0.f;
        float cnt1 = (rr + 1 < nvalid) ? d_cnt[n0 + rr + 1] : 0.f;
        float2 h0 = (rr     < nvalid) ? *(const float2*)(d_h + (size_t)(n0 + rr)     * 64 + c0) : make_float2(0.f, 0.f);
        float2 h1 = (rr + 1 < nvalid) ? *(const float2*)(d_h + (size_t)(n0 + rr + 1) * 64 + c0) : make_float2(0.f, 0.f);
        float2 v0 = upk2(acc[p][0]);
        float2 v1 = upk2(acc[p][1]);
        buf[(c0    ) * BS + rr    ] = v0.x + cnt0 * sbm2[c0    ] + h0.x;
        buf[(c0    ) * BS + rr + 1] = v0.y + cnt1 * sbm2[c0    ] + h1.x;
        buf[(c0 + 1) * BS + rr    ] = v1.x + cnt0 * sbm2[c0 + 1] + h0.y;
        buf[(c0 + 1) * BS + rr + 1] = v1.y + cnt1 * sbm2[c0 + 1] + h1.y;
    }
    __syncthreads();

    if (tid < 64 && tid < nvalid) {
        int r = tid;
        float s = 0.f, s2 = 0.f;
        for (int c = 0; c < 64; c++) { float x = buf[c * BS + r]; s += x; s2 += x * x; }
        float mu = s * (1.f / 64.f);
        float var = s2 * (1.f / 64.f) - mu * mu;
        float rs = rsqrtf(var + 1e-5f);
        for (int c = 0; c < 64; c++) {
            float x = buf[c * BS + r];
            buf[c * BS + r] = (x - mu) * rs * sgn[c] + sbn[c];
        }
    }
    __syncthreads();

    {
        int c = tid & 63, q = tid >> 6;
        float s = 0.f, m = -FLT_MAX;
        int rbeg = q * 16;
        int rend = min(rbeg + 16, nvalid);
        for (int r = rbeg; r < rend; r++) {
            float v = buf[c * BS + r];
            s += v;
            m = fmaxf(m, v);
        }
        red_s[q * 64 + c] = s;
        red_m[q * 64 + c] = m;
    }
    __syncthreads();
    if (tid < 64) {
        float s = red_s[tid] + red_s[64 + tid] + red_s[128 + tid] + red_s[192 + tid];
        float m = fmaxf(fmaxf(red_m[tid], red_m[64 + tid]),
                        fmaxf(red_m[128 + tid], red_m[192 + tid]));
        atomicAdd(&d_colsum[tid], s);
        atomicMaxFloat(&d_colmax[tid], m);
    }
}

__global__ void k_final(const float* __restrict__ Wg1, const float* __restrict__ bg1,
                        const float* __restrict__ Wg2, const float* __restrict__ bg2,
                        float* __restrict__ out)
{
    __shared__ float sg[128], st[64];
    int t = threadIdx.x;
    if (t < 64)       sg[t] = d_colsum[t] * (1.0f / (float)Nn);
    else if (t < 128) sg[t] = __int_as_float(d_colmax[t - 64]);
    __syncthreads();
    if (t < 64) {
        float s = bg1[t];
        for (int k = 0; k < 128; k++) s += sg[k] * Wg1[k * 64 + t];
        st[t] = fmaxf(s, 0.f);
    }
    __syncthreads();
    if (t < 64) {
        float s = bg2[t];
        for (int k = 0; k < 64; k++) s += st[k] * Wg2[k * 64 + t];
        out[t] = s;
    }
}

extern "C" void kernel_launch(void* const* d_in, const int* in_sizes, int n_in,
                              void* d_out, int out_size)
{
    const float* X      = (const float*)d_in[0];
    const float* edges  = (const float*)d_in[1];
    const float* W1     = (const float*)d_in[2];
    const float* b1     = (const float*)d_in[3];
    const float* g1     = (const float*)d_in[4];
    const float* be1    = (const float*)d_in[5];
    const float* W2     = (const float*)d_in[6];
    const float* b2     = (const float*)d_in[7];
    const float* rel_emb= (const float*)d_in[8];
    const float* Wm1    = (const float*)d_in[9];
    const float* bm1    = (const float*)d_in[10];
    const float* Wm2    = (const float*)d_in[11];
    const float* bm2    = (const float*)d_in[12];
    const float* gn     = (const float*)d_in[13];
    const float* bn     = (const float*)d_in[14];
    const float* Wg1    = (const float*)d_in[15];
    const float* bg1    = (const float*)d_in[16];
    const float* Wg2    = (const float*)d_in[17];
    const float* bg2    = (const float*)d_in[18];
    float* out = (float*)d_out;

    static int smem_set = 0;
    int node_smem = (128 * BS2 + 64 * 64) * (int)sizeof(float);
    if (!smem_set) {
        cudaFuncSetAttribute(k_node, cudaFuncAttributeMaxDynamicSharedMemorySize, node_smem);
        smem_set = 1;
    }

    k_relC<<<1, 512>>>(rel_emb, Wm1);
    int node_blocks = (Nn + TR - 1) / TR;
    k_node<<<node_blocks, 256, node_smem>>>(X, W1, b1, g1, be1, W2, b2, Wm1);
    int eblocks = ((Ee / 2) * 16 + 255) / 256;
    k_edge<<<eblocks, 256>>>(edges, Wm1, bm1);
    int nblocks = (Nn + TILE - 1) / TILE;
    k_agg<<<nblocks, 256>>>(Wm2, bm2, gn, bn);
    k_final<<<1, 128>>>(Wg1, bg1, Wg2, bg2, out);
}